// round 9
// baseline (speedup 1.0000x reference)
#include <cuda_runtime.h>
#include <cuda_bf16.h>
#include <cstdint>
#include <cstddef>

// Problem constants
#define BB    4
#define CIN   256
#define HH    56
#define WW    56
#define COUT  256
#define KK9   9
#define OCH   18
#define P     (HH*WW)     // 3136
#define NTOT  (BB*P)      // 12544
#define KDIM  (CIN*KK9)   // 2304

#define NCHUNK 16
#define CCH    (CIN/NCHUNK)   // 16

// GEMM tiling (bf16 split, 3 passes), BK=16, 4-stage pipeline
#define BM   128
#define BN   64
#define BK   16
#define NKC  (KDIM/BK)    // 144
#define NSTAGE 4

// padded smem rows (bytes)
#define A_ROWB 48                    // 16 bf16 = 32B + 16B pad (3-granule stride, conflict-free)
#define B_ROWB 144                   // 64 bf16 = 128B + 16B pad (proven)
#define A_PLANE (BM*A_ROWB)          // 6144
#define B_PLANE (BK*B_ROWB)          // 2304
#define A_LO_OFF A_PLANE
#define B_HI_OFF (2*A_PLANE)         // 12288
#define B_LO_OFF (2*A_PLANE+B_PLANE) // 14592
#define BUF_BYTES (2*A_PLANE+2*B_PLANE)   // 16896
#define SMEM_TOTAL (NSTAGE*BUF_BYTES)     // 67584 -> 3 CTAs/SM

// offconv strips
#define SY_N  (HH/4)
#define STRIPS (BB*SY_N*WW)

// Scratch (device globals)
__device__ __align__(16) float g_OffP[NCHUNK * BB * OCH * P];
__device__ __align__(16) __nv_bfloat16 g_Shi[(size_t)KDIM * NTOT];
__device__ __align__(16) __nv_bfloat16 g_Slo[(size_t)KDIM * NTOT];
__device__ __align__(16) __nv_bfloat16 g_Whi[COUT * KDIM];
__device__ __align__(16) __nv_bfloat16 g_Wlo[COUT * KDIM];

// ---------------------------------------------------------------------------
// helpers
// ---------------------------------------------------------------------------
__device__ __forceinline__ uint32_t smem_u32(const void* p) {
    uint32_t a;
    asm("{ .reg .u64 t; cvta.to.shared.u64 t, %1; cvt.u32.u64 %0, t; }" : "=r"(a) : "l"(p));
    return a;
}
__device__ __forceinline__ void cp16(uint32_t dst, const void* src) {
    asm volatile("cp.async.ca.shared.global [%0], [%1], 16;" :: "r"(dst), "l"(src) : "memory");
}
__device__ __forceinline__ void cp_commit() {
    asm volatile("cp.async.commit_group;" ::: "memory");
}
__device__ __forceinline__ void cp_wait2() {
    asm volatile("cp.async.wait_group 2;" ::: "memory");
}
__device__ __forceinline__ void cp_wait0() {
    asm volatile("cp.async.wait_group 0;" ::: "memory");
}
__device__ __forceinline__ void ldsm_x4(uint32_t* r, uint32_t addr) {
    asm volatile("ldmatrix.sync.aligned.m8n8.x4.shared.b16 {%0,%1,%2,%3}, [%4];"
                 : "=r"(r[0]), "=r"(r[1]), "=r"(r[2]), "=r"(r[3]) : "r"(addr));
}
__device__ __forceinline__ void ldsm_x4t(uint32_t* r, uint32_t addr) {
    asm volatile("ldmatrix.sync.aligned.m8n8.x4.trans.shared.b16 {%0,%1,%2,%3}, [%4];"
                 : "=r"(r[0]), "=r"(r[1]), "=r"(r[2]), "=r"(r[3]) : "r"(addr));
}
__device__ __forceinline__ void mma_bf16(float* c, const uint32_t* a, uint32_t b0, uint32_t b1) {
    asm volatile("mma.sync.aligned.m16n8k16.row.col.f32.bf16.bf16.f32 "
                 "{%0,%1,%2,%3}, {%4,%5,%6,%7}, {%8,%9}, {%0,%1,%2,%3};"
                 : "+f"(c[0]), "+f"(c[1]), "+f"(c[2]), "+f"(c[3])
                 : "r"(a[0]), "r"(a[1]), "r"(a[2]), "r"(a[3]), "r"(b0), "r"(b1));
}

// ---------------------------------------------------------------------------
// Kernel 0: weight -> bf16 hi/lo split
// ---------------------------------------------------------------------------
__global__ __launch_bounds__(256) void wconv_kernel(const float* __restrict__ w) {
    int i = blockIdx.x * 256 + threadIdx.x;
    if (i >= COUT * KDIM) return;
    float v = w[i];
    __nv_bfloat16 hi = __float2bfloat16_rn(v);
    __nv_bfloat16 lo = __float2bfloat16_rn(v - __bfloat162float(hi));
    g_Whi[i] = hi;
    g_Wlo[i] = lo;
}

// ---------------------------------------------------------------------------
// Kernel 1: offset conv, 4-row strips (verified)
// ---------------------------------------------------------------------------
__global__ __launch_bounds__(256) void offconv_kernel(
    const float* __restrict__ x, const float* __restrict__ off_w,
    const float* __restrict__ off_b)
{
    __shared__ __align__(16) float ws[OCH * CCH * KK9];
    const int tid   = threadIdx.x;
    const int chunk = blockIdx.y;
    const int ci0   = chunk * CCH;

    for (int i = tid; i < OCH * CCH * KK9; i += 256) {
        int oc  = i / (CCH * KK9);
        int rem = i % (CCH * KK9);
        int cl  = rem / KK9;
        int t   = rem % KK9;
        ws[i] = off_w[((size_t)(oc * CIN + ci0 + cl)) * KK9 + t];
    }
    __syncthreads();

    const int id = blockIdx.x * 256 + tid;
    if (id >= STRIPS) return;
    const int b   = id / (SY_N * WW);
    const int s   = id % (SY_N * WW);
    const int sy  = s / WW;
    const int sx  = s % WW;
    const int y0r = sy * 4;

    float acc[OCH][4];
#pragma unroll
    for (int oc = 0; oc < OCH; oc++) {
        float bias = (chunk == 0) ? off_b[oc] : 0.0f;
#pragma unroll
        for (int r = 0; r < 4; r++) acc[oc][r] = bias;
    }

    const float* xb = x + ((size_t)(b * CIN + ci0)) * P;
    for (int cl = 0; cl < CCH; cl++) {
        const float* xc = xb + (size_t)cl * P;
        float v[6][3];
#pragma unroll
        for (int dy = 0; dy < 6; dy++) {
            int y = y0r - 1 + dy;
#pragma unroll
            for (int dx = 0; dx < 3; dx++) {
                int xx = sx - 1 + dx;
                v[dy][dx] = (y >= 0 && y < HH && xx >= 0 && xx < WW)
                          ? xc[y * WW + xx] : 0.0f;
            }
        }
        const float* wsc = ws + cl * KK9;
#pragma unroll
        for (int oc = 0; oc < OCH; oc++) {
            const float* wo = wsc + oc * (CCH * KK9);
#pragma unroll
            for (int t = 0; t < KK9; t++) {
                float w = wo[t];
                int ty = t / 3, tx = t % 3;
#pragma unroll
                for (int r = 0; r < 4; r++)
                    acc[oc][r] = fmaf(v[r + ty][tx], w, acc[oc][r]);
            }
        }
    }

    float* op = g_OffP + (((size_t)chunk * BB + b) * OCH) * P;
#pragma unroll
    for (int oc = 0; oc < OCH; oc++) {
#pragma unroll
        for (int r = 0; r < 4; r++)
            op[(size_t)oc * P + (y0r + r) * WW + sx] = acc[oc][r];
    }
}

// ---------------------------------------------------------------------------
// Kernel 2: bilinear sampling -> S hi/lo bf16, layout [k=ci*9+kk][n=b*P+p]
// ---------------------------------------------------------------------------
__global__ __launch_bounds__(256) void sample_kernel(const float* __restrict__ x)
{
    const int tid = threadIdx.x;
    const int p   = blockIdx.x * 256 + tid;
    if (p >= P) return;
    const int b  = blockIdx.y;
    const int kk = blockIdx.z;

    float offy = 0.0f, offx = 0.0f;
#pragma unroll
    for (int c = 0; c < NCHUNK; c++) {
        const float* op = g_OffP + (((size_t)c * BB + b) * OCH + 2 * kk) * P + p;
        offy += op[0];
        offx += op[P];
    }

    const int ho = p / WW;
    const int wo = p % WW;
    const float py = (float)(ho - 1 + kk / 3) + offy;
    const float px = (float)(wo - 1 + kk % 3) + offx;
    const float fy = floorf(py), fx = floorf(px);
    const int y0 = (int)fy, x0 = (int)fx;
    const int y1 = y0 + 1,  x1 = x0 + 1;
    const float ty = py - fy, tx = px - fx;

    float w00 = (1.0f - ty) * (1.0f - tx);
    float w01 = (1.0f - ty) * tx;
    float w10 = ty * (1.0f - tx);
    float w11 = ty * tx;

    const bool vy0 = (y0 >= 0 && y0 < HH), vy1 = (y1 >= 0 && y1 < HH);
    const bool vx0 = (x0 >= 0 && x0 < WW), vx1 = (x1 >= 0 && x1 < WW);
    w00 *= (vy0 && vx0) ? 1.0f : 0.0f;
    w01 *= (vy0 && vx1) ? 1.0f : 0.0f;
    w10 *= (vy1 && vx0) ? 1.0f : 0.0f;
    w11 *= (vy1 && vx1) ? 1.0f : 0.0f;

    const int cy0 = min(max(y0, 0), HH - 1), cy1 = min(max(y1, 0), HH - 1);
    const int cx0 = min(max(x0, 0), WW - 1), cx1 = min(max(x1, 0), WW - 1);
    const int i00 = cy0 * WW + cx0, i01 = cy0 * WW + cx1;
    const int i10 = cy1 * WW + cx0, i11 = cy1 * WW + cx1;

    const float* xb = x + (size_t)b * CIN * P;
    const size_t base = (size_t)kk * NTOT + (size_t)b * P + p;
    const size_t srow = (size_t)KK9 * NTOT;

#pragma unroll 4
    for (int ci = 0; ci < CIN; ci++) {
        const float* xc = xb + (size_t)ci * P;
        float v = w00 * __ldg(xc + i00) + w01 * __ldg(xc + i01)
                + w10 * __ldg(xc + i10) + w11 * __ldg(xc + i11);
        __nv_bfloat16 hi = __float2bfloat16_rn(v);
        __nv_bfloat16 lo = __float2bfloat16_rn(v - __bfloat162float(hi));
        g_Shi[base + (size_t)ci * srow] = hi;
        g_Slo[base + (size_t)ci * srow] = lo;
    }
}

// ---------------------------------------------------------------------------
// Kernel 3: mma.sync bf16-split GEMM, BK=16, 4-stage ring, 3-chunk lead,
// one __syncthreads per chunk.
// ---------------------------------------------------------------------------
__global__ __launch_bounds__(256, 3) void gemm_mma_kernel(float* __restrict__ out)
{
    extern __shared__ char smem[];
    const uint32_t sb = smem_u32(smem);
    const int tid  = threadIdx.x;
    const int wid  = tid >> 5;
    const int lane = tid & 31;
    const int wm   = wid & 3;
    const int wn   = wid >> 2;
    const int n0   = blockIdx.x * BN;
    const int m0   = blockIdx.y * BM;

    float acc[2][4][4];
#pragma unroll
    for (int i = 0; i < 2; i++)
#pragma unroll
        for (int j = 0; j < 4; j++)
#pragma unroll
            for (int q = 0; q < 4; q++) acc[i][j][q] = 0.0f;

    // --- prefetch assignments: A 128 rows x 2 granules (1/thread/plane);
    //     B 16 rows x 8 granules, threads 0..127 (2 planes each) ---
    const int ar = tid >> 1, ac = tid & 1;
    const bool doB = tid < 128;
    const int br = (tid >> 3) & 15, bc = tid & 7;
    const __nv_bfloat16* pAh = g_Whi + (size_t)(m0 + ar) * KDIM + ac * 8;
    const __nv_bfloat16* pAl = g_Wlo + (size_t)(m0 + ar) * KDIM + ac * 8;
    const __nv_bfloat16* pBh = g_Shi + (size_t)br * NTOT + n0 + bc * 8;
    const __nv_bfloat16* pBl = g_Slo + (size_t)br * NTOT + n0 + bc * 8;
    const uint32_t dA = ar * A_ROWB + ac * 16;
    const uint32_t dB = br * B_ROWB + bc * 16;

    // ldmatrix per-thread address components
    const int lrow  = lane & 15;
    const int lhalf = lane >> 4;
    const uint32_t a_base = (uint32_t)(wm * 32 + lrow) * A_ROWB + lhalf * 16;
    const uint32_t b_base = (uint32_t)lrow * B_ROWB + (uint32_t)(wn * 32 + lhalf * 8) * 2;

    // preload chunks 0..2 into stages 0..2 (one commit group each)
#pragma unroll
    for (int s = 0; s < 3; s++) {
        const uint32_t st = sb + (uint32_t)s * BUF_BYTES;
        cp16(st + dA, pAh);
        cp16(st + A_LO_OFF + dA, pAl);
        if (doB) {
            cp16(st + B_HI_OFF + dB, pBh);
            cp16(st + B_LO_OFF + dB, pBl);
        }
        pAh += BK; pAl += BK;
        pBh += (size_t)BK * NTOT; pBl += (size_t)BK * NTOT;
        cp_commit();
    }

#pragma unroll 1
    for (int kc = 0; kc < NKC; kc++) {
        cp_wait2();              // chunk kc's group complete (3-group lead)
        __syncthreads();         // everyone done computing chunk kc-1 (stage (kc-1)%4)
        if (kc + 3 < NKC) {      // prefetch chunk kc+3 into stage (kc+3)%4 == (kc-1)%4
            const uint32_t nb = sb + (uint32_t)((kc + 3) % NSTAGE) * BUF_BYTES;
            cp16(nb + dA, pAh);
            cp16(nb + A_LO_OFF + dA, pAl);
            if (doB) {
                cp16(nb + B_HI_OFF + dB, pBh);
                cp16(nb + B_LO_OFF + dB, pBl);
            }
            pAh += BK; pAl += BK;
            pBh += (size_t)BK * NTOT; pBl += (size_t)BK * NTOT;
        }
        cp_commit();             // one group per iteration (possibly empty)

        const uint32_t buf = sb + (uint32_t)(kc % NSTAGE) * BUF_BYTES;
        uint32_t Ah[2][4], Al[2][4], Bh[2][4], Bl[2][4];
#pragma unroll
        for (int mt = 0; mt < 2; mt++) {
            uint32_t aaddr = buf + a_base + (uint32_t)mt * 16 * A_ROWB;
            ldsm_x4(Ah[mt], aaddr);
            ldsm_x4(Al[mt], aaddr + A_LO_OFF);
        }
#pragma unroll
        for (int bq = 0; bq < 2; bq++) {
            uint32_t baddr = buf + B_HI_OFF + b_base + (uint32_t)bq * 32;
            ldsm_x4t(Bh[bq], baddr);
            ldsm_x4t(Bl[bq], baddr + (B_LO_OFF - B_HI_OFF));
        }
#pragma unroll
        for (int mt = 0; mt < 2; mt++) {
#pragma unroll
            for (int bq = 0; bq < 2; bq++) {
#pragma unroll
                for (int h = 0; h < 2; h++) {
                    int nt = bq * 2 + h;
                    mma_bf16(acc[mt][nt], Ah[mt], Bh[bq][2*h], Bh[bq][2*h+1]);
                    mma_bf16(acc[mt][nt], Ah[mt], Bl[bq][2*h], Bl[bq][2*h+1]);
                    mma_bf16(acc[mt][nt], Al[mt], Bh[bq][2*h], Bh[bq][2*h+1]);
                }
            }
        }
    }
    cp_wait0();

    const int g = lane >> 2;
    const int t = lane & 3;
    const int bidx = n0 / P;
    const int pofs = n0 % P;
#pragma unroll
    for (int mt = 0; mt < 2; mt++) {
        int mrow = m0 + wm * 32 + mt * 16 + g;
        float* r0 = out + ((size_t)(bidx * COUT + mrow)) * P + pofs;
        float* r1 = r0 + 8 * P;
#pragma unroll
        for (int nt = 0; nt < 4; nt++) {
            int col = wn * 32 + nt * 8 + 2 * t;
            *(float2*)(r0 + col) = make_float2(acc[mt][nt][0], acc[mt][nt][1]);
            *(float2*)(r1 + col) = make_float2(acc[mt][nt][2], acc[mt][nt][3]);
        }
    }
}

// ---------------------------------------------------------------------------
extern "C" void kernel_launch(void* const* d_in, const int* in_sizes, int n_in,
                              void* d_out, int out_size)
{
    const float* x     = (const float*)d_in[0];
    const float* wgt   = (const float*)d_in[1];
    const float* off_w = (const float*)d_in[2];
    const float* off_b = (const float*)d_in[3];
    float* out = (float*)d_out;

    cudaFuncSetAttribute(gemm_mma_kernel, cudaFuncAttributeMaxDynamicSharedMemorySize, SMEM_TOTAL);

    wconv_kernel<<<(COUT * KDIM + 255) / 256, 256>>>(wgt);

    dim3 g1((STRIPS + 255) / 256, NCHUNK);
    offconv_kernel<<<g1, 256>>>(x, off_w, off_b);

    dim3 g2((P + 255) / 256, BB, KK9);
    sample_kernel<<<g2, 256>>>(x);

    dim3 g3(NTOT / BN, COUT / BM);
    gemm_mma_kernel<<<g3, 256, SMEM_TOTAL>>>(out);
}

// round 10
// speedup vs baseline: 1.3433x; 1.3433x over previous
#include <cuda_runtime.h>
#include <cuda_bf16.h>
#include <cstdint>
#include <cstddef>

// Problem constants
#define BB    4
#define CIN   256
#define HH    56
#define WW    56
#define COUT  256
#define KK9   9
#define OCH   18
#define P     (HH*WW)     // 3136
#define NTOT  (BB*P)      // 12544
#define KDIM  (CIN*KK9)   // 2304

#define NCHUNK 16
#define CCH    (CIN/NCHUNK)   // 16

// GEMM tiling (bf16 split, 3 passes): BM=128, BN=64, BK=32,
// 4 warps (128 thr), warp tile 64x32 (2M x 2N)
#define BM   128
#define BN   64
#define BK   32
#define NKC  (KDIM/BK)    // 72

// padded smem rows (bytes) — identical geometry to round 7 (proven)
#define A_ROWB 80
#define B_ROWB 144
#define A_PLANE (BM*A_ROWB)
#define B_PLANE (BK*B_ROWB)
#define A_LO_OFF A_PLANE
#define B_HI_OFF (2*A_PLANE)
#define B_LO_OFF (2*A_PLANE+B_PLANE)
#define BUF_BYTES (2*A_PLANE+2*B_PLANE)   // 29696
#define SMEM_TOTAL (2*BUF_BYTES)          // 59392 -> 3 CTAs/SM

// offconv strips
#define SY_N  (HH/4)
#define STRIPS (BB*SY_N*WW)

// Scratch (device globals)
__device__ __align__(16) float g_OffP[NCHUNK * BB * OCH * P];
__device__ __align__(16) __nv_bfloat16 g_Shi[(size_t)KDIM * NTOT];
__device__ __align__(16) __nv_bfloat16 g_Slo[(size_t)KDIM * NTOT];
__device__ __align__(16) __nv_bfloat16 g_Whi[COUT * KDIM];
__device__ __align__(16) __nv_bfloat16 g_Wlo[COUT * KDIM];

// ---------------------------------------------------------------------------
// helpers
// ---------------------------------------------------------------------------
__device__ __forceinline__ uint32_t smem_u32(const void* p) {
    uint32_t a;
    asm("{ .reg .u64 t; cvta.to.shared.u64 t, %1; cvt.u32.u64 %0, t; }" : "=r"(a) : "l"(p));
    return a;
}
__device__ __forceinline__ void cp16(uint32_t dst, const void* src) {
    asm volatile("cp.async.ca.shared.global [%0], [%1], 16;" :: "r"(dst), "l"(src) : "memory");
}
__device__ __forceinline__ void cp_commit() {
    asm volatile("cp.async.commit_group;" ::: "memory");
}
__device__ __forceinline__ void cp_wait1() {
    asm volatile("cp.async.wait_group 1;" ::: "memory");
}
__device__ __forceinline__ void cp_wait0() {
    asm volatile("cp.async.wait_group 0;" ::: "memory");
}
__device__ __forceinline__ void ldsm_x4(uint32_t* r, uint32_t addr) {
    asm volatile("ldmatrix.sync.aligned.m8n8.x4.shared.b16 {%0,%1,%2,%3}, [%4];"
                 : "=r"(r[0]), "=r"(r[1]), "=r"(r[2]), "=r"(r[3]) : "r"(addr));
}
__device__ __forceinline__ void ldsm_x4t(uint32_t* r, uint32_t addr) {
    asm volatile("ldmatrix.sync.aligned.m8n8.x4.trans.shared.b16 {%0,%1,%2,%3}, [%4];"
                 : "=r"(r[0]), "=r"(r[1]), "=r"(r[2]), "=r"(r[3]) : "r"(addr));
}
__device__ __forceinline__ void mma_bf16(float* c, const uint32_t* a, uint32_t b0, uint32_t b1) {
    asm volatile("mma.sync.aligned.m16n8k16.row.col.f32.bf16.bf16.f32 "
                 "{%0,%1,%2,%3}, {%4,%5,%6,%7}, {%8,%9}, {%0,%1,%2,%3};"
                 : "+f"(c[0]), "+f"(c[1]), "+f"(c[2]), "+f"(c[3])
                 : "r"(a[0]), "r"(a[1]), "r"(a[2]), "r"(a[3]), "r"(b0), "r"(b1));
}

// ---------------------------------------------------------------------------
// Kernel 0: weight -> bf16 hi/lo split
// ---------------------------------------------------------------------------
__global__ __launch_bounds__(256) void wconv_kernel(const float* __restrict__ w) {
    int i = blockIdx.x * 256 + threadIdx.x;
    if (i >= COUT * KDIM) return;
    float v = w[i];
    __nv_bfloat16 hi = __float2bfloat16_rn(v);
    __nv_bfloat16 lo = __float2bfloat16_rn(v - __bfloat162float(hi));
    g_Whi[i] = hi;
    g_Wlo[i] = lo;
}

// ---------------------------------------------------------------------------
// Kernel 1: offset conv, 4-row strips (verified)
// ---------------------------------------------------------------------------
__global__ __launch_bounds__(256) void offconv_kernel(
    const float* __restrict__ x, const float* __restrict__ off_w,
    const float* __restrict__ off_b)
{
    __shared__ __align__(16) float ws[OCH * CCH * KK9];
    const int tid   = threadIdx.x;
    const int chunk = blockIdx.y;
    const int ci0   = chunk * CCH;

    for (int i = tid; i < OCH * CCH * KK9; i += 256) {
        int oc  = i / (CCH * KK9);
        int rem = i % (CCH * KK9);
        int cl  = rem / KK9;
        int t   = rem % KK9;
        ws[i] = off_w[((size_t)(oc * CIN + ci0 + cl)) * KK9 + t];
    }
    __syncthreads();

    const int id = blockIdx.x * 256 + tid;
    if (id >= STRIPS) return;
    const int b   = id / (SY_N * WW);
    const int s   = id % (SY_N * WW);
    const int sy  = s / WW;
    const int sx  = s % WW;
    const int y0r = sy * 4;

    float acc[OCH][4];
#pragma unroll
    for (int oc = 0; oc < OCH; oc++) {
        float bias = (chunk == 0) ? off_b[oc] : 0.0f;
#pragma unroll
        for (int r = 0; r < 4; r++) acc[oc][r] = bias;
    }

    const float* xb = x + ((size_t)(b * CIN + ci0)) * P;
    for (int cl = 0; cl < CCH; cl++) {
        const float* xc = xb + (size_t)cl * P;
        float v[6][3];
#pragma unroll
        for (int dy = 0; dy < 6; dy++) {
            int y = y0r - 1 + dy;
#pragma unroll
            for (int dx = 0; dx < 3; dx++) {
                int xx = sx - 1 + dx;
                v[dy][dx] = (y >= 0 && y < HH && xx >= 0 && xx < WW)
                          ? xc[y * WW + xx] : 0.0f;
            }
        }
        const float* wsc = ws + cl * KK9;
#pragma unroll
        for (int oc = 0; oc < OCH; oc++) {
            const float* wo = wsc + oc * (CCH * KK9);
#pragma unroll
            for (int t = 0; t < KK9; t++) {
                float w = wo[t];
                int ty = t / 3, tx = t % 3;
#pragma unroll
                for (int r = 0; r < 4; r++)
                    acc[oc][r] = fmaf(v[r + ty][tx], w, acc[oc][r]);
            }
        }
    }

    float* op = g_OffP + (((size_t)chunk * BB + b) * OCH) * P;
#pragma unroll
    for (int oc = 0; oc < OCH; oc++) {
#pragma unroll
        for (int r = 0; r < 4; r++)
            op[(size_t)oc * P + (y0r + r) * WW + sx] = acc[oc][r];
    }
}

// ---------------------------------------------------------------------------
// Kernel 2: bilinear sampling -> S hi/lo bf16, layout [k=ci*9+kk][n=b*P+p]
// ---------------------------------------------------------------------------
__global__ __launch_bounds__(256) void sample_kernel(const float* __restrict__ x)
{
    const int tid = threadIdx.x;
    const int p   = blockIdx.x * 256 + tid;
    if (p >= P) return;
    const int b  = blockIdx.y;
    const int kk = blockIdx.z;

    float offy = 0.0f, offx = 0.0f;
#pragma unroll
    for (int c = 0; c < NCHUNK; c++) {
        const float* op = g_OffP + (((size_t)c * BB + b) * OCH + 2 * kk) * P + p;
        offy += op[0];
        offx += op[P];
    }

    const int ho = p / WW;
    const int wo = p % WW;
    const float py = (float)(ho - 1 + kk / 3) + offy;
    const float px = (float)(wo - 1 + kk % 3) + offx;
    const float fy = floorf(py), fx = floorf(px);
    const int y0 = (int)fy, x0 = (int)fx;
    const int y1 = y0 + 1,  x1 = x0 + 1;
    const float ty = py - fy, tx = px - fx;

    float w00 = (1.0f - ty) * (1.0f - tx);
    float w01 = (1.0f - ty) * tx;
    float w10 = ty * (1.0f - tx);
    float w11 = ty * tx;

    const bool vy0 = (y0 >= 0 && y0 < HH), vy1 = (y1 >= 0 && y1 < HH);
    const bool vx0 = (x0 >= 0 && x0 < WW), vx1 = (x1 >= 0 && x1 < WW);
    w00 *= (vy0 && vx0) ? 1.0f : 0.0f;
    w01 *= (vy0 && vx1) ? 1.0f : 0.0f;
    w10 *= (vy1 && vx0) ? 1.0f : 0.0f;
    w11 *= (vy1 && vx1) ? 1.0f : 0.0f;

    const int cy0 = min(max(y0, 0), HH - 1), cy1 = min(max(y1, 0), HH - 1);
    const int cx0 = min(max(x0, 0), WW - 1), cx1 = min(max(x1, 0), WW - 1);
    const int i00 = cy0 * WW + cx0, i01 = cy0 * WW + cx1;
    const int i10 = cy1 * WW + cx0, i11 = cy1 * WW + cx1;

    const float* xb = x + (size_t)b * CIN * P;
    const size_t base = (size_t)kk * NTOT + (size_t)b * P + p;
    const size_t srow = (size_t)KK9 * NTOT;

#pragma unroll 4
    for (int ci = 0; ci < CIN; ci++) {
        const float* xc = xb + (size_t)ci * P;
        float v = w00 * __ldg(xc + i00) + w01 * __ldg(xc + i01)
                + w10 * __ldg(xc + i10) + w11 * __ldg(xc + i11);
        __nv_bfloat16 hi = __float2bfloat16_rn(v);
        __nv_bfloat16 lo = __float2bfloat16_rn(v - __bfloat162float(hi));
        g_Shi[base + (size_t)ci * srow] = hi;
        g_Slo[base + (size_t)ci * srow] = lo;
    }
}

// ---------------------------------------------------------------------------
// Kernel 3: mma.sync bf16-split GEMM. Round-7 pipeline (2-stage, BK=32),
// but 4 warps / 128 threads, warp tile 64x32 (2M x 2N) -> 18% less L1
// traffic per MMA.
// ---------------------------------------------------------------------------
__global__ __launch_bounds__(128, 3) void gemm_mma_kernel(float* __restrict__ out)
{
    extern __shared__ char smem[];
    const uint32_t sb = smem_u32(smem);
    const int tid  = threadIdx.x;
    const int wid  = tid >> 5;
    const int lane = tid & 31;
    const int wm   = wid & 1;      // 2 warps in M
    const int wn   = wid >> 1;     // 2 warps in N
    const int n0   = blockIdx.x * BN;
    const int m0   = blockIdx.y * BM;

    float acc[4][4][4];            // [mt 0..3][nt 0..3][quad]
#pragma unroll
    for (int i = 0; i < 4; i++)
#pragma unroll
        for (int j = 0; j < 4; j++)
#pragma unroll
            for (int q = 0; q < 4; q++) acc[i][j][q] = 0.0f;

    // --- prefetch assignments (128 threads) ---
    // A: 128 rows x 4 granules x 2 planes  (4 iters/thread/plane)
    // B: 32 rows x 8 granules x 2 planes   (2 iters/thread/plane)
    // running pointers
    const __nv_bfloat16* pW = g_Whi + (size_t)m0 * KDIM;
    const __nv_bfloat16* pWl = g_Wlo + (size_t)m0 * KDIM;
    const __nv_bfloat16* pS = g_Shi + n0;
    const __nv_bfloat16* pSl = g_Slo + n0;

    // ldmatrix per-thread address components
    const int lrow  = lane & 15;
    const int lhalf = lane >> 4;
    const uint32_t a_base = (uint32_t)(wm * 64 + lrow) * A_ROWB + lhalf * 16;
    const uint32_t b_base = (uint32_t)lrow * B_ROWB + (uint32_t)(wn * 32 + lhalf * 8) * 2;

    // stage loader
    auto load_stage = [&](uint32_t st, int k0) {
#pragma unroll
        for (int it = 0; it < 4; it++) {
            int idx = it * 128 + tid;          // 0..511
            int row = idx >> 2;
            int c   = idx & 3;
            uint32_t d = row * A_ROWB + c * 16;
            cp16(st + d, pW + (size_t)row * KDIM + k0 + c * 8);
            cp16(st + A_LO_OFF + d, pWl + (size_t)row * KDIM + k0 + c * 8);
        }
#pragma unroll
        for (int it = 0; it < 2; it++) {
            int idx = it * 128 + tid;          // 0..255
            int row = idx >> 3;
            int c   = idx & 7;
            uint32_t d = row * B_ROWB + c * 16;
            cp16(st + B_HI_OFF + d, pS + (size_t)(k0 + row) * NTOT + c * 8);
            cp16(st + B_LO_OFF + d, pSl + (size_t)(k0 + row) * NTOT + c * 8);
        }
    };

    load_stage(sb, 0);
    cp_commit();

#pragma unroll 1
    for (int kc = 0; kc < NKC; kc++) {
        const uint32_t buf = sb + (uint32_t)(kc & 1) * BUF_BYTES;
        if (kc < NKC - 1) {
            load_stage(sb + (uint32_t)((kc + 1) & 1) * BUF_BYTES, (kc + 1) * BK);
            cp_commit();
            cp_wait1();
        } else {
            cp_wait0();
        }
        __syncthreads();

#pragma unroll
        for (int kk = 0; kk < 2; kk++) {
            uint32_t Ah[4][4], Al[4][4], Bh[2][4], Bl[2][4];
#pragma unroll
            for (int mt = 0; mt < 4; mt++) {
                uint32_t aaddr = buf + a_base + (uint32_t)mt * 16 * A_ROWB + kk * 32;
                ldsm_x4(Ah[mt], aaddr);
                ldsm_x4(Al[mt], aaddr + A_LO_OFF);
            }
#pragma unroll
            for (int bq = 0; bq < 2; bq++) {
                uint32_t baddr = buf + B_HI_OFF + b_base + (uint32_t)kk * 16 * B_ROWB + bq * 32;
                ldsm_x4t(Bh[bq], baddr);
                ldsm_x4t(Bl[bq], baddr + (B_LO_OFF - B_HI_OFF));
            }
#pragma unroll
            for (int mt = 0; mt < 4; mt++) {
#pragma unroll
                for (int bq = 0; bq < 2; bq++) {
#pragma unroll
                    for (int h = 0; h < 2; h++) {
                        int nt = bq * 2 + h;
                        mma_bf16(acc[mt][nt], Ah[mt], Bh[bq][2*h], Bh[bq][2*h+1]);
                        mma_bf16(acc[mt][nt], Ah[mt], Bl[bq][2*h], Bl[bq][2*h+1]);
                        mma_bf16(acc[mt][nt], Al[mt], Bh[bq][2*h], Bh[bq][2*h+1]);
                    }
                }
            }
        }
        __syncthreads();
    }

    const int g = lane >> 2;
    const int t = lane & 3;
    const int bidx = n0 / P;
    const int pofs = n0 % P;
#pragma unroll
    for (int mt = 0; mt < 4; mt++) {
        int mrow = m0 + wm * 64 + mt * 16 + g;
        float* r0 = out + ((size_t)(bidx * COUT + mrow)) * P + pofs;
        float* r1 = r0 + 8 * P;
#pragma unroll
        for (int nt = 0; nt < 4; nt++) {
            int col = wn * 32 + nt * 8 + 2 * t;
            *(float2*)(r0 + col) = make_float2(acc[mt][nt][0], acc[mt][nt][1]);
            *(float2*)(r1 + col) = make_float2(acc[mt][nt][2], acc[mt][nt][3]);
        }
    }
}

// ---------------------------------------------------------------------------
extern "C" void kernel_launch(void* const* d_in, const int* in_sizes, int n_in,
                              void* d_out, int out_size)
{
    const float* x     = (const float*)d_in[0];
    const float* wgt   = (const float*)d_in[1];
    const float* off_w = (const float*)d_in[2];
    const float* off_b = (const float*)d_in[3];
    float* out = (float*)d_out;

    cudaFuncSetAttribute(gemm_mma_kernel, cudaFuncAttributeMaxDynamicSharedMemorySize, SMEM_TOTAL);

    wconv_kernel<<<(COUT * KDIM + 255) / 256, 256>>>(wgt);

    dim3 g1((STRIPS + 255) / 256, NCHUNK);
    offconv_kernel<<<g1, 256>>>(x, off_w, off_b);

    dim3 g2((P + 255) / 256, BB, KK9);
    sample_kernel<<<g2, 256>>>(x);

    dim3 g3(NTOT / BN, COUT / BM);
    gemm_mma_kernel<<<g3, 128, SMEM_TOTAL>>>(out);
}

// round 11
// speedup vs baseline: 1.9360x; 1.4412x over previous
#include <cuda_runtime.h>
#include <cuda_fp16.h>
#include <cstdint>
#include <cstddef>

// Problem constants
#define BB    4
#define CIN   256
#define HH    56
#define WW    56
#define COUT  256
#define KK9   9
#define OCH   18
#define P     (HH*WW)     // 3136
#define NTOT  (BB*P)      // 12544
#define KDIM  (CIN*KK9)   // 2304

#define NCHUNK 16
#define CCH    (CIN/NCHUNK)   // 16

// GEMM tiling (fp16 single pass): BM=128, BN=64, BK=64,
// 4 warps (128 thr), warp tile 64x32 (2M x 2N)
#define BM   128
#define BN   64
#define BK   64
#define NKC  (KDIM/BK)    // 36

// padded smem rows (bytes): 64 fp16 = 128B data + 16B pad (144 proven conflict-free)
#define A_ROWB 144
#define B_ROWB 144
#define A_PLANE (BM*A_ROWB)          // 18432
#define B_PLANE (BK*B_ROWB)          // 9216
#define B_OFF   A_PLANE
#define BUF_BYTES (A_PLANE+B_PLANE)  // 27648
#define SMEM_TOTAL (2*BUF_BYTES)     // 55296 -> 3 CTAs/SM smem-wise

// offconv strips
#define SY_N  (HH/4)
#define STRIPS (BB*SY_N*WW)

// Scratch (device globals)
__device__ __align__(16) float g_OffP[NCHUNK * BB * OCH * P];
__device__ __align__(16) __half g_S[(size_t)KDIM * NTOT];   // fp16 samples
__device__ __align__(16) __half g_W[COUT * KDIM];           // fp16 weights

// ---------------------------------------------------------------------------
// helpers
// ---------------------------------------------------------------------------
__device__ __forceinline__ uint32_t smem_u32(const void* p) {
    uint32_t a;
    asm("{ .reg .u64 t; cvta.to.shared.u64 t, %1; cvt.u32.u64 %0, t; }" : "=r"(a) : "l"(p));
    return a;
}
__device__ __forceinline__ void cp16(uint32_t dst, const void* src) {
    asm volatile("cp.async.ca.shared.global [%0], [%1], 16;" :: "r"(dst), "l"(src) : "memory");
}
__device__ __forceinline__ void cp_commit() {
    asm volatile("cp.async.commit_group;" ::: "memory");
}
__device__ __forceinline__ void cp_wait1() {
    asm volatile("cp.async.wait_group 1;" ::: "memory");
}
__device__ __forceinline__ void cp_wait0() {
    asm volatile("cp.async.wait_group 0;" ::: "memory");
}
__device__ __forceinline__ void ldsm_x4(uint32_t* r, uint32_t addr) {
    asm volatile("ldmatrix.sync.aligned.m8n8.x4.shared.b16 {%0,%1,%2,%3}, [%4];"
                 : "=r"(r[0]), "=r"(r[1]), "=r"(r[2]), "=r"(r[3]) : "r"(addr));
}
__device__ __forceinline__ void ldsm_x4t(uint32_t* r, uint32_t addr) {
    asm volatile("ldmatrix.sync.aligned.m8n8.x4.trans.shared.b16 {%0,%1,%2,%3}, [%4];"
                 : "=r"(r[0]), "=r"(r[1]), "=r"(r[2]), "=r"(r[3]) : "r"(addr));
}
__device__ __forceinline__ void mma_f16(float* c, const uint32_t* a, uint32_t b0, uint32_t b1) {
    asm volatile("mma.sync.aligned.m16n8k16.row.col.f32.f16.f16.f32 "
                 "{%0,%1,%2,%3}, {%4,%5,%6,%7}, {%8,%9}, {%0,%1,%2,%3};"
                 : "+f"(c[0]), "+f"(c[1]), "+f"(c[2]), "+f"(c[3])
                 : "r"(a[0]), "r"(a[1]), "r"(a[2]), "r"(a[3]), "r"(b0), "r"(b1));
}

// ---------------------------------------------------------------------------
// Kernel 0: weight -> fp16
// ---------------------------------------------------------------------------
__global__ __launch_bounds__(256) void wconv_kernel(const float* __restrict__ w) {
    int i = blockIdx.x * 256 + threadIdx.x;
    if (i >= COUT * KDIM) return;
    g_W[i] = __float2half_rn(w[i]);
}

// ---------------------------------------------------------------------------
// Kernel 1: offset conv, 4-row strips (verified)
// ---------------------------------------------------------------------------
__global__ __launch_bounds__(256) void offconv_kernel(
    const float* __restrict__ x, const float* __restrict__ off_w,
    const float* __restrict__ off_b)
{
    __shared__ __align__(16) float ws[OCH * CCH * KK9];
    const int tid   = threadIdx.x;
    const int chunk = blockIdx.y;
    const int ci0   = chunk * CCH;

    for (int i = tid; i < OCH * CCH * KK9; i += 256) {
        int oc  = i / (CCH * KK9);
        int rem = i % (CCH * KK9);
        int cl  = rem / KK9;
        int t   = rem % KK9;
        ws[i] = off_w[((size_t)(oc * CIN + ci0 + cl)) * KK9 + t];
    }
    __syncthreads();

    const int id = blockIdx.x * 256 + tid;
    if (id >= STRIPS) return;
    const int b   = id / (SY_N * WW);
    const int s   = id % (SY_N * WW);
    const int sy  = s / WW;
    const int sx  = s % WW;
    const int y0r = sy * 4;

    float acc[OCH][4];
#pragma unroll
    for (int oc = 0; oc < OCH; oc++) {
        float bias = (chunk == 0) ? off_b[oc] : 0.0f;
#pragma unroll
        for (int r = 0; r < 4; r++) acc[oc][r] = bias;
    }

    const float* xb = x + ((size_t)(b * CIN + ci0)) * P;
    for (int cl = 0; cl < CCH; cl++) {
        const float* xc = xb + (size_t)cl * P;
        float v[6][3];
#pragma unroll
        for (int dy = 0; dy < 6; dy++) {
            int y = y0r - 1 + dy;
#pragma unroll
            for (int dx = 0; dx < 3; dx++) {
                int xx = sx - 1 + dx;
                v[dy][dx] = (y >= 0 && y < HH && xx >= 0 && xx < WW)
                          ? xc[y * WW + xx] : 0.0f;
            }
        }
        const float* wsc = ws + cl * KK9;
#pragma unroll
        for (int oc = 0; oc < OCH; oc++) {
            const float* wo = wsc + oc * (CCH * KK9);
#pragma unroll
            for (int t = 0; t < KK9; t++) {
                float w = wo[t];
                int ty = t / 3, tx = t % 3;
#pragma unroll
                for (int r = 0; r < 4; r++)
                    acc[oc][r] = fmaf(v[r + ty][tx], w, acc[oc][r]);
            }
        }
    }

    float* op = g_OffP + (((size_t)chunk * BB + b) * OCH) * P;
#pragma unroll
    for (int oc = 0; oc < OCH; oc++) {
#pragma unroll
        for (int r = 0; r < 4; r++)
            op[(size_t)oc * P + (y0r + r) * WW + sx] = acc[oc][r];
    }
}

// ---------------------------------------------------------------------------
// Kernel 2: bilinear sampling -> fp16 S[k=ci*9+kk][n=b*P+p]
// ---------------------------------------------------------------------------
__global__ __launch_bounds__(256) void sample_kernel(const float* __restrict__ x)
{
    const int tid = threadIdx.x;
    const int p   = blockIdx.x * 256 + tid;
    if (p >= P) return;
    const int b  = blockIdx.y;
    const int kk = blockIdx.z;

    float offy = 0.0f, offx = 0.0f;
#pragma unroll
    for (int c = 0; c < NCHUNK; c++) {
        const float* op = g_OffP + (((size_t)c * BB + b) * OCH + 2 * kk) * P + p;
        offy += op[0];
        offx += op[P];
    }

    const int ho = p / WW;
    const int wo = p % WW;
    const float py = (float)(ho - 1 + kk / 3) + offy;
    const float px = (float)(wo - 1 + kk % 3) + offx;
    const float fy = floorf(py), fx = floorf(px);
    const int y0 = (int)fy, x0 = (int)fx;
    const int y1 = y0 + 1,  x1 = x0 + 1;
    const float ty = py - fy, tx = px - fx;

    float w00 = (1.0f - ty) * (1.0f - tx);
    float w01 = (1.0f - ty) * tx;
    float w10 = ty * (1.0f - tx);
    float w11 = ty * tx;

    const bool vy0 = (y0 >= 0 && y0 < HH), vy1 = (y1 >= 0 && y1 < HH);
    const bool vx0 = (x0 >= 0 && x0 < WW), vx1 = (x1 >= 0 && x1 < WW);
    w00 *= (vy0 && vx0) ? 1.0f : 0.0f;
    w01 *= (vy0 && vx1) ? 1.0f : 0.0f;
    w10 *= (vy1 && vx0) ? 1.0f : 0.0f;
    w11 *= (vy1 && vx1) ? 1.0f : 0.0f;

    const int cy0 = min(max(y0, 0), HH - 1), cy1 = min(max(y1, 0), HH - 1);
    const int cx0 = min(max(x0, 0), WW - 1), cx1 = min(max(x1, 0), WW - 1);
    const int i00 = cy0 * WW + cx0, i01 = cy0 * WW + cx1;
    const int i10 = cy1 * WW + cx0, i11 = cy1 * WW + cx1;

    const float* xb = x + (size_t)b * CIN * P;
    const size_t base = (size_t)kk * NTOT + (size_t)b * P + p;
    const size_t srow = (size_t)KK9 * NTOT;

#pragma unroll 4
    for (int ci = 0; ci < CIN; ci++) {
        const float* xc = xb + (size_t)ci * P;
        float v = w00 * __ldg(xc + i00) + w01 * __ldg(xc + i01)
                + w10 * __ldg(xc + i10) + w11 * __ldg(xc + i11);
        g_S[base + (size_t)ci * srow] = __float2half_rn(v);
    }
}

// ---------------------------------------------------------------------------
// Kernel 3: single-pass fp16 mma.sync GEMM. BK=64, 2-stage, 4 warps,
// warp tile 64x32.
// ---------------------------------------------------------------------------
__global__ __launch_bounds__(128, 3) void gemm_mma_kernel(float* __restrict__ out)
{
    extern __shared__ char smem[];
    const uint32_t sb = smem_u32(smem);
    const int tid  = threadIdx.x;
    const int wid  = tid >> 5;
    const int lane = tid & 31;
    const int wm   = wid & 1;      // 2 warps in M
    const int wn   = wid >> 1;     // 2 warps in N
    const int n0   = blockIdx.x * BN;
    const int m0   = blockIdx.y * BM;

    float acc[4][4][4];
#pragma unroll
    for (int i = 0; i < 4; i++)
#pragma unroll
        for (int j = 0; j < 4; j++)
#pragma unroll
            for (int q = 0; q < 4; q++) acc[i][j][q] = 0.0f;

    const __half* pW = g_W + (size_t)m0 * KDIM;
    const __half* pS = g_S + n0;

    // ldmatrix per-thread address components
    const int lrow  = lane & 15;
    const int lhalf = lane >> 4;
    const uint32_t a_base = (uint32_t)(wm * 64 + lrow) * A_ROWB + lhalf * 16;
    const uint32_t b_base = (uint32_t)lrow * B_ROWB + (uint32_t)(wn * 32 + lhalf * 8) * 2;

    // stage loader: A 128 rows x 8 granules (8/thread), B 64 rows x 8 granules (4/thread)
    auto load_stage = [&](uint32_t st, int k0) {
#pragma unroll
        for (int it = 0; it < 8; it++) {
            int idx = it * 128 + tid;          // 0..1023
            int row = idx >> 3;
            int c   = idx & 7;
            cp16(st + row * A_ROWB + c * 16, pW + (size_t)row * KDIM + k0 + c * 8);
        }
#pragma unroll
        for (int it = 0; it < 4; it++) {
            int idx = it * 128 + tid;          // 0..511
            int row = idx >> 3;
            int c   = idx & 7;
            cp16(st + B_OFF + row * B_ROWB + c * 16, pS + (size_t)(k0 + row) * NTOT + c * 8);
        }
    };

    load_stage(sb, 0);
    cp_commit();

#pragma unroll 1
    for (int kc = 0; kc < NKC; kc++) {
        const uint32_t buf = sb + (uint32_t)(kc & 1) * BUF_BYTES;
        if (kc < NKC - 1) {
            load_stage(sb + (uint32_t)((kc + 1) & 1) * BUF_BYTES, (kc + 1) * BK);
            cp_commit();
            cp_wait1();
        } else {
            cp_wait0();
        }
        __syncthreads();

#pragma unroll
        for (int kk = 0; kk < 4; kk++) {       // four k16 steps per BK=64 chunk
            uint32_t A[4][4], B[2][4];
#pragma unroll
            for (int mt = 0; mt < 4; mt++)
                ldsm_x4(A[mt], buf + a_base + (uint32_t)mt * 16 * A_ROWB + kk * 32);
#pragma unroll
            for (int bq = 0; bq < 2; bq++)
                ldsm_x4t(B[bq], buf + B_OFF + b_base + (uint32_t)kk * 16 * B_ROWB + bq * 32);
#pragma unroll
            for (int mt = 0; mt < 4; mt++) {
#pragma unroll
                for (int bq = 0; bq < 2; bq++) {
#pragma unroll
                    for (int h = 0; h < 2; h++) {
                        int nt = bq * 2 + h;
                        mma_f16(acc[mt][nt], A[mt], B[bq][2*h], B[bq][2*h+1]);
                    }
                }
            }
        }
        __syncthreads();
    }

    const int g = lane >> 2;
    const int t = lane & 3;
    const int bidx = n0 / P;
    const int pofs = n0 % P;
#pragma unroll
    for (int mt = 0; mt < 4; mt++) {
        int mrow = m0 + wm * 64 + mt * 16 + g;
        float* r0 = out + ((size_t)(bidx * COUT + mrow)) * P + pofs;
        float* r1 = r0 + 8 * P;
#pragma unroll
        for (int nt = 0; nt < 4; nt++) {
            int col = wn * 32 + nt * 8 + 2 * t;
            *(float2*)(r0 + col) = make_float2(acc[mt][nt][0], acc[mt][nt][1]);
            *(float2*)(r1 + col) = make_float2(acc[mt][nt][2], acc[mt][nt][3]);
        }
    }
}

// ---------------------------------------------------------------------------
extern "C" void kernel_launch(void* const* d_in, const int* in_sizes, int n_in,
                              void* d_out, int out_size)
{
    const float* x     = (const float*)d_in[0];
    const float* wgt   = (const float*)d_in[1];
    const float* off_w = (const float*)d_in[2];
    const float* off_b = (const float*)d_in[3];
    float* out = (float*)d_out;

    cudaFuncSetAttribute(gemm_mma_kernel, cudaFuncAttributeMaxDynamicSharedMemorySize, SMEM_TOTAL);

    wconv_kernel<<<(COUT * KDIM + 255) / 256, 256>>>(wgt);

    dim3 g1((STRIPS + 255) / 256, NCHUNK);
    offconv_kernel<<<g1, 256>>>(x, off_w, off_b);

    dim3 g2((P + 255) / 256, BB, KK9);
    sample_kernel<<<g2, 256>>>(x);

    dim3 g3(NTOT / BN, COUT / BM);
    gemm_mma_kernel<<<g3, 128, SMEM_TOTAL>>>(out);
}